// round 6
// baseline (speedup 1.0000x reference)
#include <cuda_runtime.h>
#include <cuda_fp16.h>
#include <math.h>

#define BN    8192
#define HID   128
#define NE    262144
#define NRBF  64
#define NBLK  4
#define TLEN  2048
#define RCUTF 6.0f
#define GAMMAF (10.0f/36.0f)

// ---- scratch (device globals: allocation-free) ----
__device__ float  g_h[BN * HID];
__device__ float  g_x[BN * HID];
__device__ float  g_agg[BN * HID];
__device__ float  g_u[NE];
__device__ __half g_tab[NBLK * TLEN * HID];     // 2 MB fp16 filter table
// CSR (built once per launch)
__device__ int    g_cnt[BN];
__device__ int    g_cnt2[BN];
__device__ int    g_off[BN + 1];
__device__ int    g_esrc[NE];
__device__ float  g_eu[NE];

__device__ __forceinline__ float silu_f(float v) { return v / (1.0f + expf(-v)); }

// ---------------------------------------------------------------- embed
__global__ void k_embed(const int* __restrict__ Z, const float* __restrict__ embed_w) {
    int n = blockIdx.x, j = threadIdx.x;
    g_h[n * HID + j] = embed_w[Z[n] * HID + j];
}

// ---------------------------------------------------------------- distances + dst histogram
__global__ void k_zero_cnt() {
    int i = blockIdx.x * blockDim.x + threadIdx.x;
    if (i < BN) { g_cnt[i] = 0; g_cnt2[i] = 0; }
}

__global__ void k_dist(const int* __restrict__ ei, const float* __restrict__ pos) {
    int e = blockIdx.x * blockDim.x + threadIdx.x;
    if (e >= NE) return;
    int s = ei[e], d = ei[NE + e];
    float dx = pos[3*s]   - pos[3*d];
    float dy = pos[3*s+1] - pos[3*d+1];
    float dz = pos[3*s+2] - pos[3*d+2];
    float dd = sqrtf(dx*dx + dy*dy + dz*dz);
    dd = fminf(dd, RCUTF);
    g_u[e] = dd * ((float)(TLEN - 1) / RCUTF);
    atomicAdd(&g_cnt[d], 1);
}

// ---------------------------------------------------------------- exclusive scan of 8192 bins
__global__ void k_scan() {   // 1 block, 1024 threads
    __shared__ int sm[1024];
    int t = threadIdx.x;
    int base = t * 8;
    int loc[8];
    int s = 0;
    #pragma unroll
    for (int i = 0; i < 8; i++) { loc[i] = s; s += g_cnt[base + i]; }
    sm[t] = s;
    __syncthreads();
    for (int off = 1; off < 1024; off <<= 1) {
        int v = (t >= off) ? sm[t - off] : 0;
        __syncthreads();
        sm[t] += v;
        __syncthreads();
    }
    int pre = (t == 0) ? 0 : sm[t - 1];
    #pragma unroll
    for (int i = 0; i < 8; i++) g_off[base + i] = pre + loc[i];
    if (t == 1023) g_off[BN] = sm[1023];
}

// ---------------------------------------------------------------- scatter edges into CSR
__global__ void k_scatter(const int* __restrict__ ei) {
    int e = blockIdx.x * blockDim.x + threadIdx.x;
    if (e >= NE) return;
    int s = ei[e], d = ei[NE + e];
    int p = g_off[d] + atomicAdd(&g_cnt2[d], 1);
    g_esrc[p] = s;
    g_eu[p]   = g_u[e];
}

// ================================================================
// GEMM tiles: 32 rows x 128 cols, 256 threads, thread tile 2x8.
// cg = tid&15 (cols cg*8..+7), rg = tid>>4 (rows rg*2, rg*2+1)
// ================================================================

#define GEMM_BODY(SRC, KDIM)                                              \
    int cg = tid & 15, rg = tid >> 4;                                     \
    float acc[2][8];                                                      \
    _Pragma("unroll")                                                     \
    for (int r = 0; r < 2; r++)                                           \
        _Pragma("unroll")                                                 \
        for (int c = 0; c < 8; c++) acc[r][c] = 0.0f;                     \
    _Pragma("unroll 4")                                                   \
    for (int k = 0; k < KDIM; k++) {                                      \
        float4 w0 = ((const float4*)(Ws + k * 128))[cg * 2];              \
        float4 w1v = ((const float4*)(Ws + k * 128))[cg * 2 + 1];         \
        _Pragma("unroll")                                                 \
        for (int r = 0; r < 2; r++) {                                     \
            float a = SRC[(rg * 2 + r) * KDIM + k];                       \
            acc[r][0] += a * w0.x;  acc[r][1] += a * w0.y;                \
            acc[r][2] += a * w0.z;  acc[r][3] += a * w0.w;                \
            acc[r][4] += a * w1v.x; acc[r][5] += a * w1v.y;               \
            acc[r][6] += a * w1v.z; acc[r][7] += a * w1v.w;               \
        }                                                                 \
    }

// ---------------------------------------------------------------- tables: w_i(d), fp16 out
// grid (TLEN/32, NBLK), block 256; smem rbf[32*64] + act[32*128] + Ws[128*128]
__global__ void k_table_f(const float* __restrict__ w1, const float* __restrict__ b1,
                          const float* __restrict__ w2, const float* __restrict__ b2) {
    extern __shared__ float sm[];
    float* rbfs = sm;                    // 32*64
    float* act  = sm + 32*64;            // 32*128
    float* Ws   = sm + 32*64 + 32*128;   // 128*128
    int tid = threadIdx.x;
    int blk = blockIdx.y;
    int t0  = blockIdx.x * 32;
    const float DSTEP = RCUTF / (float)(TLEN - 1);
    const float CSTEP = RCUTF / (float)(NRBF - 1);

    for (int i = tid; i < 32 * 64; i += 256) {
        int row = i >> 6, c = i & 63;
        float d = (float)(t0 + row) * DSTEP;
        float u = d - (float)c * CSTEP;
        rbfs[i] = expf(-GAMMAF * u * u);
    }
    {
        const float4* W4 = (const float4*)(w1 + blk * NRBF * HID);
        float4* Ws4 = (float4*)Ws;
        for (int i = tid; i < NRBF * 32; i += 256) Ws4[i] = W4[i];
    }
    __syncthreads();

    {
        GEMM_BODY(rbfs, NRBF)
        float bb[8];
        #pragma unroll
        for (int c = 0; c < 8; c++) bb[c] = __ldg(&b1[blk * HID + cg * 8 + c]);
        #pragma unroll
        for (int r = 0; r < 2; r++)
            #pragma unroll
            for (int c = 0; c < 8; c++)
                act[(rg * 2 + r) * 128 + cg * 8 + c] = silu_f(acc[r][c] + bb[c]);
    }
    __syncthreads();
    {
        const float4* W4 = (const float4*)(w2 + blk * HID * HID);
        float4* Ws4 = (float4*)Ws;
        for (int i = tid; i < HID * 32; i += 256) Ws4[i] = W4[i];
    }
    __syncthreads();
    {
        GEMM_BODY(act, HID)
        float bb[8];
        #pragma unroll
        for (int c = 0; c < 8; c++) bb[c] = __ldg(&b2[blk * HID + cg * 8 + c]);
        #pragma unroll
        for (int r = 0; r < 2; r++) {
            __half2* dst = (__half2*)(g_tab + (size_t)(blk * TLEN + t0 + rg * 2 + r) * HID + cg * 8);
            dst[0] = __floats2half2_rn(acc[r][0] + bb[0], acc[r][1] + bb[1]);
            dst[1] = __floats2half2_rn(acc[r][2] + bb[2], acc[r][3] + bb[3]);
            dst[2] = __floats2half2_rn(acc[r][4] + bb[4], acc[r][5] + bb[5]);
            dst[3] = __floats2half2_rn(acc[r][6] + bb[6], acc[r][7] + bb[7]);
        }
    }
}

// ---------------------------------------------------------------- x = h @ lin_in
// grid BN/32, block 256; smem hs[32*128] + Ws[128*128]
__global__ void k_xgemm_f(const float* __restrict__ W) {
    extern __shared__ float sm[];
    float* hs = sm;                   // 32*128
    float* Ws = sm + 32 * 128;        // 128*128
    int tid = threadIdx.x;
    int row0 = blockIdx.x * 32;
    {
        const float4* s4 = (const float4*)(g_h + (size_t)row0 * HID);
        float4* d4 = (float4*)hs;
        for (int i = tid; i < 32 * 32; i += 256) d4[i] = s4[i];
        const float4* W4 = (const float4*)W;
        float4* Ws4 = (float4*)Ws;
        for (int i = tid; i < HID * 32; i += 256) Ws4[i] = W4[i];
    }
    __syncthreads();
    GEMM_BODY(hs, HID)
    #pragma unroll
    for (int r = 0; r < 2; r++) {
        float* dst = g_x + (size_t)(row0 + rg * 2 + r) * HID + cg * 8;
        float4 o0 = {acc[r][0], acc[r][1], acc[r][2], acc[r][3]};
        float4 o1 = {acc[r][4], acc[r][5], acc[r][6], acc[r][7]};
        ((float4*)dst)[0] = o0;
        ((float4*)dst)[1] = o1;
    }
}

// ---------------------------------------------------------------- CSR edge aggregation
// warp per dst node; lane owns 4 channels; no atomics; 2-edge unroll for MLP
__device__ __forceinline__ void edge_accum(const uint2* __restrict__ tb, int lane,
                                           float u, int s, float4& acc) {
    int i0 = (int)u;
    if (i0 > TLEN - 2) i0 = TLEN - 2;
    float f = u - (float)i0;
    const uint2* r = tb + (size_t)i0 * 32 + lane;
    uint2 ua = __ldg(r);
    uint2 ub = __ldg(r + 32);
    float2 a01 = __half22float2(*reinterpret_cast<const __half2*>(&ua.x));
    float2 a23 = __half22float2(*reinterpret_cast<const __half2*>(&ua.y));
    float2 b01 = __half22float2(*reinterpret_cast<const __half2*>(&ub.x));
    float2 b23 = __half22float2(*reinterpret_cast<const __half2*>(&ub.y));
    float4 xv = __ldg((const float4*)(g_x + (size_t)s * HID) + lane);
    acc.x += (a01.x + f * (b01.x - a01.x)) * xv.x;
    acc.y += (a01.y + f * (b01.y - a01.y)) * xv.y;
    acc.z += (a23.x + f * (b23.x - a23.x)) * xv.z;
    acc.w += (a23.y + f * (b23.y - a23.y)) * xv.w;
}

__global__ void k_edge_csr(int blk) {
    int w    = (blockIdx.x * blockDim.x + threadIdx.x) >> 5;
    int lane = threadIdx.x & 31;
    if (w >= BN) return;
    int p0 = g_off[w], p1 = g_off[w + 1];
    float4 acc0 = {0.f, 0.f, 0.f, 0.f};
    float4 acc1 = {0.f, 0.f, 0.f, 0.f};
    const uint2* tb = (const uint2*)(g_tab + (size_t)blk * TLEN * HID);
    int p = p0;
    for (; p + 2 <= p1; p += 2) {
        float u0 = __ldg(&g_eu[p]);
        float u1 = __ldg(&g_eu[p + 1]);
        int   s0 = __ldg(&g_esrc[p]);
        int   s1 = __ldg(&g_esrc[p + 1]);
        edge_accum(tb, lane, u0, s0, acc0);
        edge_accum(tb, lane, u1, s1, acc1);
    }
    if (p < p1) {
        float u0 = __ldg(&g_eu[p]);
        int   s0 = __ldg(&g_esrc[p]);
        edge_accum(tb, lane, u0, s0, acc0);
    }
    acc0.x += acc1.x; acc0.y += acc1.y; acc0.z += acc1.z; acc0.w += acc1.w;
    ((float4*)(g_agg + (size_t)w * HID))[lane] = acc0;
}

// ---------------------------------------------------------------- fused node MLP + residual + LN
// grid BN/32, block 256; smem ins[32*128] + act[32*128] + Ws[128*128]
__global__ void k_node_f(const float* __restrict__ W1, const float* __restrict__ B1,
                         const float* __restrict__ W2, const float* __restrict__ B2,
                         const float* __restrict__ G,  const float* __restrict__ Bt) {
    extern __shared__ float sm[];
    float* ins = sm;                    // 32*128
    float* act = sm + 32 * 128;         // 32*128
    float* Ws  = sm + 2 * 32 * 128;     // 128*128
    int tid = threadIdx.x;
    int row0 = blockIdx.x * 32;
    {
        const float4* s4 = (const float4*)(g_agg + (size_t)row0 * HID);
        float4* d4 = (float4*)ins;
        for (int i = tid; i < 32 * 32; i += 256) d4[i] = s4[i];
        const float4* W4 = (const float4*)W1;
        float4* Ws4 = (float4*)Ws;
        for (int i = tid; i < HID * 32; i += 256) Ws4[i] = W4[i];
    }
    __syncthreads();
    {
        GEMM_BODY(ins, HID)
        float bb[8];
        #pragma unroll
        for (int c = 0; c < 8; c++) bb[c] = __ldg(&B1[cg * 8 + c]);
        #pragma unroll
        for (int r = 0; r < 2; r++)
            #pragma unroll
            for (int c = 0; c < 8; c++)
                act[(rg * 2 + r) * 128 + cg * 8 + c] = silu_f(acc[r][c] + bb[c]);
    }
    __syncthreads();
    {
        const float4* W4 = (const float4*)W2;
        float4* Ws4 = (float4*)Ws;
        for (int i = tid; i < HID * 32; i += 256) Ws4[i] = W4[i];
    }
    __syncthreads();
    {
        GEMM_BODY(act, HID)
        float bb[8];
        #pragma unroll
        for (int c = 0; c < 8; c++) bb[c] = __ldg(&B2[cg * 8 + c]);
        // y = h + out, staged into ins for the LN pass
        #pragma unroll
        for (int r = 0; r < 2; r++) {
            int row = row0 + rg * 2 + r;
            const float* hp = g_h + (size_t)row * HID + cg * 8;
            #pragma unroll
            for (int c = 0; c < 8; c++)
                ins[(rg * 2 + r) * 128 + cg * 8 + c] = acc[r][c] + bb[c] + __ldg(&hp[c]);
        }
    }
    __syncthreads();

    // layernorm: 8 threads per row, 16 ch each
    int r = tid >> 3, q = tid & 7;
    const float4* yr = (const float4*)(ins + r * 128 + q * 16);
    float s = 0.0f, ssq = 0.0f;
    float4 v[4];
    #pragma unroll
    for (int i = 0; i < 4; i++) {
        v[i] = yr[i];
        s   += v[i].x + v[i].y + v[i].z + v[i].w;
        ssq += v[i].x*v[i].x + v[i].y*v[i].y + v[i].z*v[i].z + v[i].w*v[i].w;
    }
    #pragma unroll
    for (int off = 1; off < 8; off <<= 1) {
        s   += __shfl_xor_sync(0xffffffffu, s, off);
        ssq += __shfl_xor_sync(0xffffffffu, ssq, off);
    }
    float mu = s * (1.0f / HID);
    float var = ssq * (1.0f / HID) - mu * mu;
    float rstd = rsqrtf(var + 1e-5f);
    float4* outp = (float4*)(g_h + (size_t)(row0 + r) * HID + q * 16);
    const float4* G4 = (const float4*)(G + q * 16);
    const float4* B4 = (const float4*)(Bt + q * 16);
    #pragma unroll
    for (int i = 0; i < 4; i++) {
        float4 gv = __ldg(&G4[i]);
        float4 bv = __ldg(&B4[i]);
        float4 o;
        o.x = (v[i].x - mu) * rstd * gv.x + bv.x;
        o.y = (v[i].y - mu) * rstd * gv.y + bv.y;
        o.z = (v[i].z - mu) * rstd * gv.z + bv.z;
        o.w = (v[i].w - mu) * rstd * gv.w + bv.w;
        outp[i] = o;
    }
}

// ---------------------------------------------------------------- output zero + readout
__global__ void k_zero_out(float* out) {
    if (threadIdx.x < 64) out[threadIdx.x] = 0.0f;
}

__global__ void k_readout(const float* __restrict__ w1, const float* __restrict__ b1v,
                          const float* __restrict__ w2, const float* __restrict__ b2v,
                          float* __restrict__ out) {
    __shared__ float s[HID];
    __shared__ float part[2];
    int n = blockIdx.x, t = threadIdx.x;   // 64 threads
    float h0 = g_h[n * HID + t];
    float h1 = g_h[n * HID + 64 + t];
    s[t]      = silu_f(h0);
    s[64 + t] = silu_f(h1);
    __syncthreads();
    float a = b1v[t];
    #pragma unroll 8
    for (int k = 0; k < HID; k++) a += s[k] * w1[k * 64 + t];
    float v = silu_f(a) * w2[t];
    #pragma unroll
    for (int off = 16; off > 0; off >>= 1) v += __shfl_down_sync(0xffffffffu, v, off);
    if ((t & 31) == 0) part[t >> 5] = v;
    __syncthreads();
    if (t == 0) atomicAdd(&out[n >> 7], part[0] + part[1] + b2v[0]);
}

// ---------------------------------------------------------------- launch
extern "C" void kernel_launch(void* const* d_in, const int* in_sizes, int n_in,
                              void* d_out, int out_size) {
    const int*   Z       = (const int*)  d_in[0];
    const float* pos     = (const float*)d_in[1];
    const int*   ei      = (const int*)  d_in[2];
    const float* embed_w = (const float*)d_in[3];
    const float* ew1     = (const float*)d_in[4];
    const float* eb1     = (const float*)d_in[5];
    const float* ew2     = (const float*)d_in[6];
    const float* eb2     = (const float*)d_in[7];
    const float* linw    = (const float*)d_in[8];
    const float* nw1     = (const float*)d_in[9];
    const float* nb1     = (const float*)d_in[10];
    const float* nw2     = (const float*)d_in[11];
    const float* nb2     = (const float*)d_in[12];
    const float* lng     = (const float*)d_in[13];
    const float* lnb     = (const float*)d_in[14];
    const float* row1    = (const float*)d_in[15];
    const float* rob1    = (const float*)d_in[16];
    const float* row2    = (const float*)d_in[17];
    const float* rob2    = (const float*)d_in[18];
    float* out = (float*)d_out;

    const int SM_TABLE = (32*64 + 32*128 + 128*128) * (int)sizeof(float);   // 88 KB
    const int SM_XGEMM = (32*128 + 128*128) * (int)sizeof(float);           // 80 KB
    const int SM_NODE  = (2*32*128 + 128*128) * (int)sizeof(float);         // 96 KB
    cudaFuncSetAttribute(k_table_f, cudaFuncAttributeMaxDynamicSharedMemorySize, SM_TABLE);
    cudaFuncSetAttribute(k_xgemm_f, cudaFuncAttributeMaxDynamicSharedMemorySize, SM_XGEMM);
    cudaFuncSetAttribute(k_node_f,  cudaFuncAttributeMaxDynamicSharedMemorySize, SM_NODE);

    // one-time per launch: embed, distances, CSR build, filter tables
    k_embed<<<BN, HID>>>(Z, embed_w);
    k_zero_cnt<<<BN / 1024, 1024>>>();
    k_dist<<<(NE + 255) / 256, 256>>>(ei, pos);
    k_scan<<<1, 1024>>>();
    k_scatter<<<(NE + 255) / 256, 256>>>(ei);
    dim3 tg(TLEN / 32, NBLK);
    k_table_f<<<tg, 256, SM_TABLE>>>(ew1, eb1, ew2, eb2);

    for (int b = 0; b < NBLK; b++) {
        k_xgemm_f<<<BN / 32, 256, SM_XGEMM>>>(linw + b * HID * HID);
        k_edge_csr<<<BN / 8, 256>>>(b);
        k_node_f<<<BN / 32, 256, SM_NODE>>>(
            nw1 + b * HID * HID, nb1 + b * HID,
            nw2 + b * HID * HID, nb2 + b * HID,
            lng + b * HID, lnb + b * HID);
    }

    k_zero_out<<<1, 64>>>(out);
    k_readout<<<BN, 64>>>(row1, rob1, row2, rob2, out);
}

// round 8
// speedup vs baseline: 1.0057x; 1.0057x over previous
#include <cuda_runtime.h>
#include <cuda_fp16.h>
#include <math.h>

#define BN    8192
#define HID   128
#define NE    262144
#define NRBF  64
#define NBLK  4
#define TLEN  2048
#define RCUTF 6.0f
#define GAMMAF (10.0f/36.0f)

// ---- scratch (device globals: allocation-free) ----
__device__ float  g_h[BN * HID];
__device__ float  g_x[BN * HID];
__device__ float  g_agg[BN * HID];
__device__ float  g_u[NE];
__device__ __half g_tab[NBLK * TLEN * HID];     // 2 MB fp16 filter table (L2-resident)

__device__ __forceinline__ float silu_f(float v) { return v / (1.0f + expf(-v)); }

// ---------------------------------------------------------------- embed
__global__ void k_embed(const int* __restrict__ Z, const float* __restrict__ embed_w) {
    int n = blockIdx.x, j = threadIdx.x;
    g_h[n * HID + j] = embed_w[Z[n] * HID + j];
}

// ---------------------------------------------------------------- distances -> table coord
__global__ void k_dist(const int* __restrict__ ei, const float* __restrict__ pos) {
    int e = blockIdx.x * blockDim.x + threadIdx.x;
    if (e >= NE) return;
    int s = ei[e], d = ei[NE + e];
    float dx = pos[3*s]   - pos[3*d];
    float dy = pos[3*s+1] - pos[3*d+1];
    float dz = pos[3*s+2] - pos[3*d+2];
    float dd = sqrtf(dx*dx + dy*dy + dz*dz);
    dd = fminf(dd, RCUTF);
    g_u[e] = dd * ((float)(TLEN - 1) / RCUTF);
}

// ================================================================
// GEMM tiles: 32 rows x 128 cols, 256 threads, thread tile 2x8.
// cg = tid&15 (cols cg*8..+7), rg = tid>>4 (rows rg*2, rg*2+1)
// ================================================================

#define GEMM_BODY(SRC, KDIM)                                              \
    int cg = tid & 15, rg = tid >> 4;                                     \
    float acc[2][8];                                                      \
    _Pragma("unroll")                                                     \
    for (int r = 0; r < 2; r++)                                           \
        _Pragma("unroll")                                                 \
        for (int c = 0; c < 8; c++) acc[r][c] = 0.0f;                     \
    _Pragma("unroll 4")                                                   \
    for (int k = 0; k < KDIM; k++) {                                      \
        float4 w0 = ((const float4*)(Ws + k * 128))[cg * 2];              \
        float4 w1v = ((const float4*)(Ws + k * 128))[cg * 2 + 1];         \
        _Pragma("unroll")                                                 \
        for (int r = 0; r < 2; r++) {                                     \
            float a = SRC[(rg * 2 + r) * KDIM + k];                       \
            acc[r][0] += a * w0.x;  acc[r][1] += a * w0.y;                \
            acc[r][2] += a * w0.z;  acc[r][3] += a * w0.w;                \
            acc[r][4] += a * w1v.x; acc[r][5] += a * w1v.y;               \
            acc[r][6] += a * w1v.z; acc[r][7] += a * w1v.w;               \
        }                                                                 \
    }

// ---------------------------------------------------------------- tables: w_i(d), fp16 out
// grid (TLEN/32, NBLK), block 256; smem rbf[32*64] + act[32*128] + Ws[128*128]
__global__ void k_table_f(const float* __restrict__ w1, const float* __restrict__ b1,
                          const float* __restrict__ w2, const float* __restrict__ b2) {
    extern __shared__ float sm[];
    float* rbfs = sm;                    // 32*64
    float* act  = sm + 32*64;            // 32*128
    float* Ws   = sm + 32*64 + 32*128;   // 128*128
    int tid = threadIdx.x;
    int blk = blockIdx.y;
    int t0  = blockIdx.x * 32;
    const float DSTEP = RCUTF / (float)(TLEN - 1);
    const float CSTEP = RCUTF / (float)(NRBF - 1);

    for (int i = tid; i < 32 * 64; i += 256) {
        int row = i >> 6, c = i & 63;
        float d = (float)(t0 + row) * DSTEP;
        float u = d - (float)c * CSTEP;
        rbfs[i] = expf(-GAMMAF * u * u);
    }
    {
        const float4* W4 = (const float4*)(w1 + blk * NRBF * HID);
        float4* Ws4 = (float4*)Ws;
        for (int i = tid; i < NRBF * 32; i += 256) Ws4[i] = W4[i];
    }
    __syncthreads();

    {
        GEMM_BODY(rbfs, NRBF)
        float bb[8];
        #pragma unroll
        for (int c = 0; c < 8; c++) bb[c] = __ldg(&b1[blk * HID + cg * 8 + c]);
        #pragma unroll
        for (int r = 0; r < 2; r++)
            #pragma unroll
            for (int c = 0; c < 8; c++)
                act[(rg * 2 + r) * 128 + cg * 8 + c] = silu_f(acc[r][c] + bb[c]);
    }
    __syncthreads();
    {
        const float4* W4 = (const float4*)(w2 + blk * HID * HID);
        float4* Ws4 = (float4*)Ws;
        for (int i = tid; i < HID * 32; i += 256) Ws4[i] = W4[i];
    }
    __syncthreads();
    {
        GEMM_BODY(act, HID)
        float bb[8];
        #pragma unroll
        for (int c = 0; c < 8; c++) bb[c] = __ldg(&b2[blk * HID + cg * 8 + c]);
        #pragma unroll
        for (int r = 0; r < 2; r++) {
            __half2* dst = (__half2*)(g_tab + (size_t)(blk * TLEN + t0 + rg * 2 + r) * HID + cg * 8);
            dst[0] = __floats2half2_rn(acc[r][0] + bb[0], acc[r][1] + bb[1]);
            dst[1] = __floats2half2_rn(acc[r][2] + bb[2], acc[r][3] + bb[3]);
            dst[2] = __floats2half2_rn(acc[r][4] + bb[4], acc[r][5] + bb[5]);
            dst[3] = __floats2half2_rn(acc[r][6] + bb[6], acc[r][7] + bb[7]);
        }
    }
}

// ---------------------------------------------------------------- x = h @ lin_in (block 0 only); zero agg
// grid BN/32, block 256; smem hs[32*128] + Ws[128*128]
__global__ void k_xgemm_f(const float* __restrict__ W) {
    extern __shared__ float sm[];
    float* hs = sm;                   // 32*128
    float* Ws = sm + 32 * 128;        // 128*128
    int tid = threadIdx.x;
    int row0 = blockIdx.x * 32;
    {
        const float4* s4 = (const float4*)(g_h + (size_t)row0 * HID);
        float4* d4 = (float4*)hs;
        for (int i = tid; i < 32 * 32; i += 256) d4[i] = s4[i];
        const float4* W4 = (const float4*)W;
        float4* Ws4 = (float4*)Ws;
        for (int i = tid; i < HID * 32; i += 256) Ws4[i] = W4[i];
    }
    __syncthreads();
    GEMM_BODY(hs, HID)
    #pragma unroll
    for (int r = 0; r < 2; r++) {
        float* dst = g_x + (size_t)(row0 + rg * 2 + r) * HID + cg * 8;
        float4 o0 = {acc[r][0], acc[r][1], acc[r][2], acc[r][3]};
        float4 o1 = {acc[r][4], acc[r][5], acc[r][6], acc[r][7]};
        ((float4*)dst)[0] = o0;
        ((float4*)dst)[1] = o1;
    }
    float4 z = {0.f, 0.f, 0.f, 0.f};
    float4* ag4 = (float4*)(g_agg + (size_t)row0 * HID);
    for (int i = tid; i < 32 * 32; i += 256) ag4[i] = z;
}

// ---------------------------------------------------------------- edge scatter (warp/edge, fp16 table, v4 red)
__global__ void k_edge(const int* __restrict__ ei, int blk) {
    int gid  = blockIdx.x * blockDim.x + threadIdx.x;
    int e    = gid >> 5;
    int lane = gid & 31;
    if (e >= NE) return;
    float u = __ldg(&g_u[e]);
    int i0 = (int)u;
    if (i0 > TLEN - 2) i0 = TLEN - 2;
    float f = u - (float)i0;
    int s = __ldg(&ei[e]), d = __ldg(&ei[NE + e]);
    const uint2* tb = (const uint2*)(g_tab + (size_t)blk * TLEN * HID);  // 32 uint2 per row
    uint2 ua = __ldg(tb + (size_t)i0 * 32 + lane);
    uint2 ub = __ldg(tb + (size_t)(i0 + 1) * 32 + lane);
    float2 a01 = __half22float2(*reinterpret_cast<const __half2*>(&ua.x));
    float2 a23 = __half22float2(*reinterpret_cast<const __half2*>(&ua.y));
    float2 b01 = __half22float2(*reinterpret_cast<const __half2*>(&ub.x));
    float2 b23 = __half22float2(*reinterpret_cast<const __half2*>(&ub.y));
    float4 xv = __ldg((const float4*)(g_x + (size_t)s * HID) + lane);
    float m0 = (a01.x + f * (b01.x - a01.x)) * xv.x;
    float m1 = (a01.y + f * (b01.y - a01.y)) * xv.y;
    float m2 = (a23.x + f * (b23.x - a23.x)) * xv.z;
    float m3 = (a23.y + f * (b23.y - a23.y)) * xv.w;
    float* ag = g_agg + (size_t)d * HID + lane * 4;
    asm volatile("red.global.add.v4.f32 [%0], {%1, %2, %3, %4};"
                 :: "l"(ag), "f"(m0), "f"(m1), "f"(m2), "f"(m3) : "memory");
}

// ---------------------------------------------------------------- fused node MLP + residual + LN
//   + (optional) x = h_new @ lin_in for the NEXT block, + agg re-zero
// grid BN/32, block 256; smem ins[32*128] + act[32*128] + Ws[128*128]
__global__ void k_node_f(const float* __restrict__ W1, const float* __restrict__ B1,
                         const float* __restrict__ W2, const float* __restrict__ B2,
                         const float* __restrict__ G,  const float* __restrict__ Bt,
                         const float* __restrict__ WlinNext, int hasNext) {
    extern __shared__ float sm[];
    float* ins = sm;                    // 32*128: agg tile -> y tile -> h_new tile
    float* act = sm + 32 * 128;         // 32*128
    float* Ws  = sm + 2 * 32 * 128;     // 128*128 (reloaded 3x)
    int tid = threadIdx.x;
    int row0 = blockIdx.x * 32;
    {
        const float4* s4 = (const float4*)(g_agg + (size_t)row0 * HID);
        float4* d4 = (float4*)ins;
        for (int i = tid; i < 32 * 32; i += 256) d4[i] = s4[i];
        const float4* W4 = (const float4*)W1;
        float4* Ws4 = (float4*)Ws;
        for (int i = tid; i < HID * 32; i += 256) Ws4[i] = W4[i];
    }
    __syncthreads();
    {
        GEMM_BODY(ins, HID)
        float bb[8];
        #pragma unroll
        for (int c = 0; c < 8; c++) bb[c] = __ldg(&B1[cg * 8 + c]);
        #pragma unroll
        for (int r = 0; r < 2; r++)
            #pragma unroll
            for (int c = 0; c < 8; c++)
                act[(rg * 2 + r) * 128 + cg * 8 + c] = silu_f(acc[r][c] + bb[c]);
    }
    __syncthreads();
    {
        const float4* W4 = (const float4*)W2;
        float4* Ws4 = (float4*)Ws;
        for (int i = tid; i < HID * 32; i += 256) Ws4[i] = W4[i];
    }
    __syncthreads();
    {
        GEMM_BODY(act, HID)
        float bb[8];
        #pragma unroll
        for (int c = 0; c < 8; c++) bb[c] = __ldg(&B2[cg * 8 + c]);
        // y = h + out, staged into ins for the LN pass
        #pragma unroll
        for (int r = 0; r < 2; r++) {
            int row = row0 + rg * 2 + r;
            const float* hp = g_h + (size_t)row * HID + cg * 8;
            #pragma unroll
            for (int c = 0; c < 8; c++)
                ins[(rg * 2 + r) * 128 + cg * 8 + c] = acc[r][c] + bb[c] + __ldg(&hp[c]);
        }
    }
    __syncthreads();

    // layernorm: 8 threads per row, 16 ch each; write h_new to gmem AND back to ins
    {
        int r = tid >> 3, q = tid & 7;
        const float4* yr = (const float4*)(ins + r * 128 + q * 16);
        float s = 0.0f, ssq = 0.0f;
        float4 v[4];
        #pragma unroll
        for (int i = 0; i < 4; i++) {
            v[i] = yr[i];
            s   += v[i].x + v[i].y + v[i].z + v[i].w;
            ssq += v[i].x*v[i].x + v[i].y*v[i].y + v[i].z*v[i].z + v[i].w*v[i].w;
        }
        #pragma unroll
        for (int off = 1; off < 8; off <<= 1) {
            s   += __shfl_xor_sync(0xffffffffu, s, off);
            ssq += __shfl_xor_sync(0xffffffffu, ssq, off);
        }
        float mu = s * (1.0f / HID);
        float var = ssq * (1.0f / HID) - mu * mu;
        float rstd = rsqrtf(var + 1e-5f);
        float4* outp = (float4*)(g_h + (size_t)(row0 + r) * HID + q * 16);
        float4* insp = (float4*)(ins + r * 128 + q * 16);
        const float4* G4 = (const float4*)(G + q * 16);
        const float4* B4 = (const float4*)(Bt + q * 16);
        #pragma unroll
        for (int i = 0; i < 4; i++) {
            float4 gv = __ldg(&G4[i]);
            float4 bv = __ldg(&B4[i]);
            float4 o;
            o.x = (v[i].x - mu) * rstd * gv.x + bv.x;
            o.y = (v[i].y - mu) * rstd * gv.y + bv.y;
            o.z = (v[i].z - mu) * rstd * gv.z + bv.z;
            o.w = (v[i].w - mu) * rstd * gv.w + bv.w;
            outp[i] = o;
            insp[i] = o;
        }
    }

    if (!hasNext) return;

    // epilogue: x = h_new @ lin_in(next block); re-zero agg tile
    {
        const float4* W4 = (const float4*)WlinNext;
        float4* Ws4 = (float4*)Ws;
        for (int i = tid; i < HID * 32; i += 256) Ws4[i] = W4[i];
    }
    __syncthreads();
    {
        GEMM_BODY(ins, HID)
        #pragma unroll
        for (int r = 0; r < 2; r++) {
            float* dst = g_x + (size_t)(row0 + rg * 2 + r) * HID + cg * 8;
            float4 o0 = {acc[r][0], acc[r][1], acc[r][2], acc[r][3]};
            float4 o1 = {acc[r][4], acc[r][5], acc[r][6], acc[r][7]};
            ((float4*)dst)[0] = o0;
            ((float4*)dst)[1] = o1;
        }
    }
    float4 z = {0.f, 0.f, 0.f, 0.f};
    float4* ag4 = (float4*)(g_agg + (size_t)row0 * HID);
    for (int i = tid; i < 32 * 32; i += 256) ag4[i] = z;
}

// ---------------------------------------------------------------- output zero + readout
__global__ void k_zero_out(float* out) {
    if (threadIdx.x < 64) out[threadIdx.x] = 0.0f;
}

__global__ void k_readout(const float* __restrict__ w1, const float* __restrict__ b1v,
                          const float* __restrict__ w2, const float* __restrict__ b2v,
                          float* __restrict__ out) {
    __shared__ float s[HID];
    __shared__ float part[2];
    int n = blockIdx.x, t = threadIdx.x;   // 64 threads
    float h0 = g_h[n * HID + t];
    float h1 = g_h[n * HID + 64 + t];
    s[t]      = silu_f(h0);
    s[64 + t] = silu_f(h1);
    __syncthreads();
    float a = b1v[t];
    #pragma unroll 8
    for (int k = 0; k < HID; k++) a += s[k] * w1[k * 64 + t];
    float v = silu_f(a) * w2[t];
    #pragma unroll
    for (int off = 16; off > 0; off >>= 1) v += __shfl_down_sync(0xffffffffu, v, off);
    if ((t & 31) == 0) part[t >> 5] = v;
    __syncthreads();
    if (t == 0) atomicAdd(&out[n >> 7], part[0] + part[1] + b2v[0]);
}

// ---------------------------------------------------------------- launch
extern "C" void kernel_launch(void* const* d_in, const int* in_sizes, int n_in,
                              void* d_out, int out_size) {
    const int*   Z       = (const int*)  d_in[0];
    const float* pos     = (const float*)d_in[1];
    const int*   ei      = (const int*)  d_in[2];
    const float* embed_w = (const float*)d_in[3];
    const float* ew1     = (const float*)d_in[4];
    const float* eb1     = (const float*)d_in[5];
    const float* ew2     = (const float*)d_in[6];
    const float* eb2     = (const float*)d_in[7];
    const float* linw    = (const float*)d_in[8];
    const float* nw1     = (const float*)d_in[9];
    const float* nb1     = (const float*)d_in[10];
    const float* nw2     = (const float*)d_in[11];
    const float* nb2     = (const float*)d_in[12];
    const float* lng     = (const float*)d_in[13];
    const float* lnb     = (const float*)d_in[14];
    const float* row1    = (const float*)d_in[15];
    const float* rob1    = (const float*)d_in[16];
    const float* row2    = (const float*)d_in[17];
    const float* rob2    = (const float*)d_in[18];
    float* out = (float*)d_out;

    const int SM_TABLE = (32*64 + 32*128 + 128*128) * (int)sizeof(float);   // 88 KB
    const int SM_XGEMM = (32*128 + 128*128) * (int)sizeof(float);           // 80 KB
    const int SM_NODE  = (2*32*128 + 128*128) * (int)sizeof(float);         // 96 KB
    cudaFuncSetAttribute(k_table_f, cudaFuncAttributeMaxDynamicSharedMemorySize, SM_TABLE);
    cudaFuncSetAttribute(k_xgemm_f, cudaFuncAttributeMaxDynamicSharedMemorySize, SM_XGEMM);
    cudaFuncSetAttribute(k_node_f,  cudaFuncAttributeMaxDynamicSharedMemorySize, SM_NODE);

    k_embed<<<BN, HID>>>(Z, embed_w);
    k_dist<<<(NE + 255) / 256, 256>>>(ei, pos);
    dim3 tg(TLEN / 32, NBLK);
    k_table_f<<<tg, 256, SM_TABLE>>>(ew1, eb1, ew2, eb2);

    // block 0 prologue: x = h @ lin_in[0], zero agg
    k_xgemm_f<<<BN / 32, 256, SM_XGEMM>>>(linw);

    for (int b = 0; b < NBLK; b++) {
        k_edge<<<NE / 8, 256>>>(ei, b);
        int hasNext = (b + 1 < NBLK) ? 1 : 0;
        const float* wnext = hasNext ? (linw + (b + 1) * HID * HID) : linw;
        k_node_f<<<BN / 32, 256, SM_NODE>>>(
            nw1 + b * HID * HID, nb1 + b * HID,
            nw2 + b * HID * HID, nb2 + b * HID,
            lng + b * HID, lnb + b * HID,
            wnext, hasNext);
    }

    k_zero_out<<<1, 64>>>(out);
    k_readout<<<BN, 64>>>(row1, rob1, row2, rob2, out);
}

// round 9
// speedup vs baseline: 1.2645x; 1.2573x over previous
#include <cuda_runtime.h>
#include <cuda_fp16.h>
#include <math.h>

#define BN    8192
#define HID   128
#define NE    262144
#define NRBF  64
#define NBLK  4
#define TLEN  2048
#define RCUTF 6.0f
#define GAMMAF (10.0f/36.0f)

// ---- scratch (device globals: allocation-free) ----
__device__ float  g_h[BN * HID];
__device__ float  g_x[BN * HID];
__device__ float  g_agg[BN * HID];
__device__ float  g_u[NE];
__device__ __half g_tab[NBLK * TLEN * HID];     // 2 MB fp16 filter table (L2-resident)

__device__ __forceinline__ float silu_f(float v) { return v / (1.0f + expf(-v)); }

// ---------------------------------------------------------------- embed
__global__ void k_embed(const int* __restrict__ Z, const float* __restrict__ embed_w) {
    int n = blockIdx.x, j = threadIdx.x;
    g_h[n * HID + j] = embed_w[Z[n] * HID + j];
}

// ---------------------------------------------------------------- distances -> table coord
__global__ void k_dist(const int* __restrict__ ei, const float* __restrict__ pos) {
    int e = blockIdx.x * blockDim.x + threadIdx.x;
    if (e >= NE) return;
    int s = ei[e], d = ei[NE + e];
    float dx = pos[3*s]   - pos[3*d];
    float dy = pos[3*s+1] - pos[3*d+1];
    float dz = pos[3*s+2] - pos[3*d+2];
    float dd = sqrtf(dx*dx + dy*dy + dz*dz);
    dd = fminf(dd, RCUTF);
    g_u[e] = dd * ((float)(TLEN - 1) / RCUTF);
}

// ================================================================
// GEMM tiles: 64 rows x 128 cols, 256 threads, thread tile 4x8 (measured best).
// cg = tid&15 (cols cg*8..+7), rg = tid>>4 (rows rg*4..+3)
// ================================================================

#define GEMM_BODY4(SRC, KDIM)                                             \
    int cg = tid & 15, rg = tid >> 4;                                     \
    float acc[4][8];                                                      \
    _Pragma("unroll")                                                     \
    for (int r = 0; r < 4; r++)                                           \
        _Pragma("unroll")                                                 \
        for (int c = 0; c < 8; c++) acc[r][c] = 0.0f;                     \
    _Pragma("unroll 4")                                                   \
    for (int k = 0; k < KDIM; k++) {                                      \
        float4 w0 = ((const float4*)(Ws + k * 128))[cg * 2];              \
        float4 w1v = ((const float4*)(Ws + k * 128))[cg * 2 + 1];         \
        _Pragma("unroll")                                                 \
        for (int r = 0; r < 4; r++) {                                     \
            float a = SRC[(rg * 4 + r) * KDIM + k];                       \
            acc[r][0] += a * w0.x;  acc[r][1] += a * w0.y;                \
            acc[r][2] += a * w0.z;  acc[r][3] += a * w0.w;                \
            acc[r][4] += a * w1v.x; acc[r][5] += a * w1v.y;               \
            acc[r][6] += a * w1v.z; acc[r][7] += a * w1v.w;               \
        }                                                                 \
    }

// ---------------------------------------------------------------- tables: w_i(d), fp16 out
// grid (TLEN/64, NBLK), block 256; smem rbf[64*64] + act[64*128] + Ws[128*128]
__global__ void k_table_f(const float* __restrict__ w1, const float* __restrict__ b1,
                          const float* __restrict__ w2, const float* __restrict__ b2) {
    extern __shared__ float sm[];
    float* rbfs = sm;                    // 64*64
    float* act  = sm + 64*64;            // 64*128
    float* Ws   = sm + 64*64 + 64*128;   // 128*128
    int tid = threadIdx.x;
    int blk = blockIdx.y;
    int t0  = blockIdx.x * 64;
    const float DSTEP = RCUTF / (float)(TLEN - 1);
    const float CSTEP = RCUTF / (float)(NRBF - 1);

    for (int i = tid; i < 64 * 64; i += 256) {
        int row = i >> 6, c = i & 63;
        float d = (float)(t0 + row) * DSTEP;
        float u = d - (float)c * CSTEP;
        rbfs[i] = expf(-GAMMAF * u * u);
    }
    {
        const float4* W4 = (const float4*)(w1 + blk * NRBF * HID);
        float4* Ws4 = (float4*)Ws;
        for (int i = tid; i < NRBF * 32; i += 256) Ws4[i] = W4[i];
    }
    __syncthreads();

    {
        GEMM_BODY4(rbfs, NRBF)
        float bb[8];
        #pragma unroll
        for (int c = 0; c < 8; c++) bb[c] = __ldg(&b1[blk * HID + cg * 8 + c]);
        #pragma unroll
        for (int r = 0; r < 4; r++)
            #pragma unroll
            for (int c = 0; c < 8; c++)
                act[(rg * 4 + r) * 128 + cg * 8 + c] = silu_f(acc[r][c] + bb[c]);
    }
    __syncthreads();
    {
        const float4* W4 = (const float4*)(w2 + blk * HID * HID);
        float4* Ws4 = (float4*)Ws;
        for (int i = tid; i < HID * 32; i += 256) Ws4[i] = W4[i];
    }
    __syncthreads();
    {
        GEMM_BODY4(act, HID)
        float bb[8];
        #pragma unroll
        for (int c = 0; c < 8; c++) bb[c] = __ldg(&b2[blk * HID + cg * 8 + c]);
        #pragma unroll
        for (int r = 0; r < 4; r++) {
            __half2* dst = (__half2*)(g_tab + (size_t)(blk * TLEN + t0 + rg * 4 + r) * HID + cg * 8);
            dst[0] = __floats2half2_rn(acc[r][0] + bb[0], acc[r][1] + bb[1]);
            dst[1] = __floats2half2_rn(acc[r][2] + bb[2], acc[r][3] + bb[3]);
            dst[2] = __floats2half2_rn(acc[r][4] + bb[4], acc[r][5] + bb[5]);
            dst[3] = __floats2half2_rn(acc[r][6] + bb[6], acc[r][7] + bb[7]);
        }
    }
}

// ---------------------------------------------------------------- x = h @ lin_in (prologue, block 0); zero agg
// grid BN/64, block 256; smem hs[64*128] + Ws[128*128]
__global__ void k_xgemm_f(const float* __restrict__ W) {
    extern __shared__ float sm[];
    float* hs = sm;                   // 64*128
    float* Ws = sm + 64 * 128;        // 128*128
    int tid = threadIdx.x;
    int row0 = blockIdx.x * 64;
    {
        const float4* s4 = (const float4*)(g_h + (size_t)row0 * HID);
        float4* d4 = (float4*)hs;
        for (int i = tid; i < 64 * 32; i += 256) d4[i] = s4[i];
        const float4* W4 = (const float4*)W;
        float4* Ws4 = (float4*)Ws;
        for (int i = tid; i < HID * 32; i += 256) Ws4[i] = W4[i];
    }
    __syncthreads();
    GEMM_BODY4(hs, HID)
    #pragma unroll
    for (int r = 0; r < 4; r++) {
        float* dst = g_x + (size_t)(row0 + rg * 4 + r) * HID + cg * 8;
        float4 o0 = {acc[r][0], acc[r][1], acc[r][2], acc[r][3]};
        float4 o1 = {acc[r][4], acc[r][5], acc[r][6], acc[r][7]};
        ((float4*)dst)[0] = o0;
        ((float4*)dst)[1] = o1;
    }
    float4 z = {0.f, 0.f, 0.f, 0.f};
    float4* ag4 = (float4*)(g_agg + (size_t)row0 * HID);
    for (int i = tid; i < 64 * 32; i += 256) ag4[i] = z;
}

// ---------------------------------------------------------------- edge scatter (warp/edge, fp16 table, v4 red)
__global__ void k_edge(const int* __restrict__ ei, int blk) {
    int gid  = blockIdx.x * blockDim.x + threadIdx.x;
    int e    = gid >> 5;
    int lane = gid & 31;
    if (e >= NE) return;
    float u = __ldg(&g_u[e]);
    int i0 = (int)u;
    if (i0 > TLEN - 2) i0 = TLEN - 2;
    float f = u - (float)i0;
    int s = __ldg(&ei[e]), d = __ldg(&ei[NE + e]);
    const uint2* tb = (const uint2*)(g_tab + (size_t)blk * TLEN * HID);  // 32 uint2 per row
    uint2 ua = __ldg(tb + (size_t)i0 * 32 + lane);
    uint2 ub = __ldg(tb + (size_t)(i0 + 1) * 32 + lane);
    float2 a01 = __half22float2(*reinterpret_cast<const __half2*>(&ua.x));
    float2 a23 = __half22float2(*reinterpret_cast<const __half2*>(&ua.y));
    float2 b01 = __half22float2(*reinterpret_cast<const __half2*>(&ub.x));
    float2 b23 = __half22float2(*reinterpret_cast<const __half2*>(&ub.y));
    float4 xv = __ldg((const float4*)(g_x + (size_t)s * HID) + lane);
    float m0 = (a01.x + f * (b01.x - a01.x)) * xv.x;
    float m1 = (a01.y + f * (b01.y - a01.y)) * xv.y;
    float m2 = (a23.x + f * (b23.x - a23.x)) * xv.z;
    float m3 = (a23.y + f * (b23.y - a23.y)) * xv.w;
    float* ag = g_agg + (size_t)d * HID + lane * 4;
    asm volatile("red.global.add.v4.f32 [%0], {%1, %2, %3, %4};"
                 :: "l"(ag), "f"(m0), "f"(m1), "f"(m2), "f"(m3) : "memory");
}

// ---------------------------------------------------------------- fused node MLP + residual + LN
//   + (if hasNext) x = h_new @ lin_in[next], re-zero agg
// grid BN/64, block 256; smem ins[64*128] + act[64*128] + Ws[128*128] = 128 KB
__global__ void k_node_f(const float* __restrict__ W1, const float* __restrict__ B1,
                         const float* __restrict__ W2, const float* __restrict__ B2,
                         const float* __restrict__ G,  const float* __restrict__ Bt,
                         const float* __restrict__ WlinNext, int hasNext) {
    extern __shared__ float sm[];
    float* ins = sm;                    // 64*128: agg -> y -> h_new
    float* act = sm + 64 * 128;         // 64*128
    float* Ws  = sm + 2 * 64 * 128;     // 128*128 (reloaded up to 3x)
    int tid = threadIdx.x;
    int row0 = blockIdx.x * 64;
    {
        const float4* s4 = (const float4*)(g_agg + (size_t)row0 * HID);
        float4* d4 = (float4*)ins;
        for (int i = tid; i < 64 * 32; i += 256) d4[i] = s4[i];
        const float4* W4 = (const float4*)W1;
        float4* Ws4 = (float4*)Ws;
        for (int i = tid; i < HID * 32; i += 256) Ws4[i] = W4[i];
    }
    __syncthreads();
    {
        GEMM_BODY4(ins, HID)
        float bb[8];
        #pragma unroll
        for (int c = 0; c < 8; c++) bb[c] = __ldg(&B1[cg * 8 + c]);
        #pragma unroll
        for (int r = 0; r < 4; r++)
            #pragma unroll
            for (int c = 0; c < 8; c++)
                act[(rg * 4 + r) * 128 + cg * 8 + c] = silu_f(acc[r][c] + bb[c]);
    }
    __syncthreads();
    {
        const float4* W4 = (const float4*)W2;
        float4* Ws4 = (float4*)Ws;
        for (int i = tid; i < HID * 32; i += 256) Ws4[i] = W4[i];
    }
    __syncthreads();
    {
        GEMM_BODY4(act, HID)
        float bb[8];
        #pragma unroll
        for (int c = 0; c < 8; c++) bb[c] = __ldg(&B2[cg * 8 + c]);
        // y = h + out, staged into ins for the LN pass
        #pragma unroll
        for (int r = 0; r < 4; r++) {
            int row = row0 + rg * 4 + r;
            const float* hp = g_h + (size_t)row * HID + cg * 8;
            #pragma unroll
            for (int c = 0; c < 8; c++)
                ins[(rg * 4 + r) * 128 + cg * 8 + c] = acc[r][c] + bb[c] + __ldg(&hp[c]);
        }
    }
    __syncthreads();

    // layernorm: 4 threads per row (64 rows), 32 ch each; write h_new to gmem AND ins
    {
        int r = tid >> 2, q = tid & 3;
        const float4* yr = (const float4*)(ins + r * 128 + q * 32);
        float s = 0.0f, ssq = 0.0f;
        float4 v[8];
        #pragma unroll
        for (int i = 0; i < 8; i++) {
            v[i] = yr[i];
            s   += v[i].x + v[i].y + v[i].z + v[i].w;
            ssq += v[i].x*v[i].x + v[i].y*v[i].y + v[i].z*v[i].z + v[i].w*v[i].w;
        }
        s   += __shfl_xor_sync(0xffffffffu, s, 1);
        ssq += __shfl_xor_sync(0xffffffffu, ssq, 1);
        s   += __shfl_xor_sync(0xffffffffu, s, 2);
        ssq += __shfl_xor_sync(0xffffffffu, ssq, 2);
        float mu = s * (1.0f / HID);
        float var = ssq * (1.0f / HID) - mu * mu;
        float rstd = rsqrtf(var + 1e-5f);
        float4* outp = (float4*)(g_h + (size_t)(row0 + r) * HID + q * 32);
        float4* insp = (float4*)(ins + r * 128 + q * 32);
        const float4* G4 = (const float4*)(G + q * 32);
        const float4* B4 = (const float4*)(Bt + q * 32);
        #pragma unroll
        for (int i = 0; i < 8; i++) {
            float4 gv = __ldg(&G4[i]);
            float4 bv = __ldg(&B4[i]);
            float4 o;
            o.x = (v[i].x - mu) * rstd * gv.x + bv.x;
            o.y = (v[i].y - mu) * rstd * gv.y + bv.y;
            o.z = (v[i].z - mu) * rstd * gv.z + bv.z;
            o.w = (v[i].w - mu) * rstd * gv.w + bv.w;
            outp[i] = o;
            insp[i] = o;
        }
    }

    if (!hasNext) return;

    // epilogue: x = h_new @ lin_in[next]; re-zero agg tile
    __syncthreads();
    {
        const float4* W4 = (const float4*)WlinNext;
        float4* Ws4 = (float4*)Ws;
        for (int i = tid; i < HID * 32; i += 256) Ws4[i] = W4[i];
    }
    __syncthreads();
    {
        GEMM_BODY4(ins, HID)
        #pragma unroll
        for (int r = 0; r < 4; r++) {
            float* dst = g_x + (size_t)(row0 + rg * 4 + r) * HID + cg * 8;
            float4 o0 = {acc[r][0], acc[r][1], acc[r][2], acc[r][3]};
            float4 o1 = {acc[r][4], acc[r][5], acc[r][6], acc[r][7]};
            ((float4*)dst)[0] = o0;
            ((float4*)dst)[1] = o1;
        }
    }
    float4 z = {0.f, 0.f, 0.f, 0.f};
    float4* ag4 = (float4*)(g_agg + (size_t)row0 * HID);
    for (int i = tid; i < 64 * 32; i += 256) ag4[i] = z;
}

// ---------------------------------------------------------------- output zero + readout
__global__ void k_zero_out(float* out) {
    if (threadIdx.x < 64) out[threadIdx.x] = 0.0f;
}

__global__ void k_readout(const float* __restrict__ w1, const float* __restrict__ b1v,
                          const float* __restrict__ w2, const float* __restrict__ b2v,
                          float* __restrict__ out) {
    __shared__ float s[HID];
    __shared__ float part[2];
    int n = blockIdx.x, t = threadIdx.x;   // 64 threads
    float h0 = g_h[n * HID + t];
    float h1 = g_h[n * HID + 64 + t];
    s[t]      = silu_f(h0);
    s[64 + t] = silu_f(h1);
    __syncthreads();
    float a = b1v[t];
    #pragma unroll 8
    for (int k = 0; k < HID; k++) a += s[k] * w1[k * 64 + t];
    float v = silu_f(a) * w2[t];
    #pragma unroll
    for (int off = 16; off > 0; off >>= 1) v += __shfl_down_sync(0xffffffffu, v, off);
    if ((t & 31) == 0) part[t >> 5] = v;
    __syncthreads();
    if (t == 0) atomicAdd(&out[n >> 7], part[0] + part[1] + b2v[0]);
}

// ---------------------------------------------------------------- launch
extern "C" void kernel_launch(void* const* d_in, const int* in_sizes, int n_in,
                              void* d_out, int out_size) {
    const int*   Z       = (const int*)  d_in[0];
    const float* pos     = (const float*)d_in[1];
    const int*   ei      = (const int*)  d_in[2];
    const float* embed_w = (const float*)d_in[3];
    const float* ew1     = (const float*)d_in[4];
    const float* eb1     = (const float*)d_in[5];
    const float* ew2     = (const float*)d_in[6];
    const float* eb2     = (const float*)d_in[7];
    const float* linw    = (const float*)d_in[8];
    const float* nw1     = (const float*)d_in[9];
    const float* nb1     = (const float*)d_in[10];
    const float* nw2     = (const float*)d_in[11];
    const float* nb2     = (const float*)d_in[12];
    const float* lng     = (const float*)d_in[13];
    const float* lnb     = (const float*)d_in[14];
    const float* row1    = (const float*)d_in[15];
    const float* rob1    = (const float*)d_in[16];
    const float* row2    = (const float*)d_in[17];
    const float* rob2    = (const float*)d_in[18];
    float* out = (float*)d_out;

    const int SM_TABLE = (64*64 + 64*128 + 128*128) * (int)sizeof(float);   // 112 KB
    const int SM_XGEMM = (64*128 + 128*128) * (int)sizeof(float);           //  96 KB
    const int SM_NODE  = (2*64*128 + 128*128) * (int)sizeof(float);         // 128 KB
    cudaFuncSetAttribute(k_table_f, cudaFuncAttributeMaxDynamicSharedMemorySize, SM_TABLE);
    cudaFuncSetAttribute(k_xgemm_f, cudaFuncAttributeMaxDynamicSharedMemorySize, SM_XGEMM);
    cudaFuncSetAttribute(k_node_f,  cudaFuncAttributeMaxDynamicSharedMemorySize, SM_NODE);

    k_embed<<<BN, HID>>>(Z, embed_w);
    k_dist<<<(NE + 255) / 256, 256>>>(ei, pos);
    dim3 tg(TLEN / 64, NBLK);
    k_table_f<<<tg, 256, SM_TABLE>>>(ew1, eb1, ew2, eb2);

    // block 0 prologue: x = h @ lin_in[0], zero agg
    k_xgemm_f<<<BN / 64, 256, SM_XGEMM>>>(linw);

    for (int b = 0; b < NBLK; b++) {
        k_edge<<<NE / 8, 256>>>(ei, b);
        int hasNext = (b + 1 < NBLK) ? 1 : 0;
        const float* wnext = hasNext ? (linw + (b + 1) * HID * HID) : linw;
        k_node_f<<<BN / 64, 256, SM_NODE>>>(
            nw1 + b * HID * HID, nb1 + b * HID,
            nw2 + b * HID * HID, nb2 + b * HID,
            lng + b * HID, lnb + b * HID,
            wnext, hasNext);
    }

    k_zero_out<<<1, 64>>>(out);
    k_readout<<<BN, 64>>>(row1, rob1, row2, rob2, out);
}

// round 10
// speedup vs baseline: 1.3625x; 1.0775x over previous
#include <cuda_runtime.h>
#include <cuda_fp16.h>
#include <math.h>

#define BN    8192
#define HID   128
#define NE    262144
#define NRBF  64
#define NBLK  4
#define TLEN  1024
#define RCUTF 6.0f
#define GAMMAF (10.0f/36.0f)
#define NT    128          // threads per GEMM block
#define TR    32           // rows per GEMM tile

// ---- scratch (device globals: allocation-free) ----
__device__ float  g_h[BN * HID];
__device__ __half g_x[BN * HID];                // fp16 x = h @ lin_in
__device__ float  g_agg[BN * HID];
__device__ float  g_u[NE];
__device__ __half g_tab[NBLK * TLEN * HID];     // 1 MB fp16 filter table (L2-resident)

__device__ __forceinline__ float silu_f(float v) { return v / (1.0f + expf(-v)); }

// ---------------------------------------------------------------- embed
__global__ void k_embed(const int* __restrict__ Z, const float* __restrict__ embed_w) {
    int n = blockIdx.x, j = threadIdx.x;
    g_h[n * HID + j] = embed_w[Z[n] * HID + j];
}

// ---------------------------------------------------------------- distances -> table coord
__global__ void k_dist(const int* __restrict__ ei, const float* __restrict__ pos) {
    int e = blockIdx.x * blockDim.x + threadIdx.x;
    if (e >= NE) return;
    int s = ei[e], d = ei[NE + e];
    float dx = pos[3*s]   - pos[3*d];
    float dy = pos[3*s+1] - pos[3*d+1];
    float dz = pos[3*s+2] - pos[3*d+2];
    float dd = sqrtf(dx*dx + dy*dy + dz*dz);
    dd = fminf(dd, RCUTF);
    g_u[e] = dd * ((float)(TLEN - 1) / RCUTF);
}

// ================================================================
// GEMM tiles: 32 rows x 128 cols, 128 threads, thread tile 4x8 (proven ILP shape).
// cg = tid&15 (cols cg*8..+7), rg = tid>>4 in 0..7 (rows rg*4..+3)
// ================================================================

#define GEMM_BODY4(SRC, KDIM)                                             \
    int cg = tid & 15, rg = tid >> 4;                                     \
    float acc[4][8];                                                      \
    _Pragma("unroll")                                                     \
    for (int r = 0; r < 4; r++)                                           \
        _Pragma("unroll")                                                 \
        for (int c = 0; c < 8; c++) acc[r][c] = 0.0f;                     \
    _Pragma("unroll 4")                                                   \
    for (int k = 0; k < KDIM; k++) {                                      \
        float4 w0 = ((const float4*)(Ws + k * 128))[cg * 2];              \
        float4 w1v = ((const float4*)(Ws + k * 128))[cg * 2 + 1];         \
        _Pragma("unroll")                                                 \
        for (int r = 0; r < 4; r++) {                                     \
            float a = SRC[(rg * 4 + r) * KDIM + k];                       \
            acc[r][0] += a * w0.x;  acc[r][1] += a * w0.y;                \
            acc[r][2] += a * w0.z;  acc[r][3] += a * w0.w;                \
            acc[r][4] += a * w1v.x; acc[r][5] += a * w1v.y;               \
            acc[r][6] += a * w1v.z; acc[r][7] += a * w1v.w;               \
        }                                                                 \
    }

// ---------------------------------------------------------------- tables: w_i(d), fp16 out
// grid (TLEN/32, NBLK), block 128; smem rbf[32*64] + act[32*128] + Ws[128*128] = 88 KB
__global__ void __launch_bounds__(NT, 2)
k_table_f(const float* __restrict__ w1, const float* __restrict__ b1,
          const float* __restrict__ w2, const float* __restrict__ b2) {
    extern __shared__ float sm[];
    float* rbfs = sm;                    // 32*64
    float* act  = sm + 32*64;            // 32*128
    float* Ws   = sm + 32*64 + 32*128;   // 128*128
    int tid = threadIdx.x;
    int blk = blockIdx.y;
    int t0  = blockIdx.x * TR;
    const float DSTEP = RCUTF / (float)(TLEN - 1);
    const float CSTEP = RCUTF / (float)(NRBF - 1);

    for (int i = tid; i < TR * 64; i += NT) {
        int row = i >> 6, c = i & 63;
        float d = (float)(t0 + row) * DSTEP;
        float u = d - (float)c * CSTEP;
        rbfs[i] = expf(-GAMMAF * u * u);
    }
    {
        const float4* W4 = (const float4*)(w1 + blk * NRBF * HID);
        float4* Ws4 = (float4*)Ws;
        for (int i = tid; i < NRBF * 32; i += NT) Ws4[i] = W4[i];
    }
    __syncthreads();

    {
        GEMM_BODY4(rbfs, NRBF)
        float bb[8];
        #pragma unroll
        for (int c = 0; c < 8; c++) bb[c] = __ldg(&b1[blk * HID + cg * 8 + c]);
        #pragma unroll
        for (int r = 0; r < 4; r++)
            #pragma unroll
            for (int c = 0; c < 8; c++)
                act[(rg * 4 + r) * 128 + cg * 8 + c] = silu_f(acc[r][c] + bb[c]);
    }
    __syncthreads();
    {
        const float4* W4 = (const float4*)(w2 + blk * HID * HID);
        float4* Ws4 = (float4*)Ws;
        for (int i = tid; i < HID * 32; i += NT) Ws4[i] = W4[i];
    }
    __syncthreads();
    {
        GEMM_BODY4(act, HID)
        float bb[8];
        #pragma unroll
        for (int c = 0; c < 8; c++) bb[c] = __ldg(&b2[blk * HID + cg * 8 + c]);
        #pragma unroll
        for (int r = 0; r < 4; r++) {
            __half2* dst = (__half2*)(g_tab + (size_t)(blk * TLEN + t0 + rg * 4 + r) * HID + cg * 8);
            dst[0] = __floats2half2_rn(acc[r][0] + bb[0], acc[r][1] + bb[1]);
            dst[1] = __floats2half2_rn(acc[r][2] + bb[2], acc[r][3] + bb[3]);
            dst[2] = __floats2half2_rn(acc[r][4] + bb[4], acc[r][5] + bb[5]);
            dst[3] = __floats2half2_rn(acc[r][6] + bb[6], acc[r][7] + bb[7]);
        }
    }
}

// ---------------------------------------------------------------- x = h @ lin_in (prologue, block 0); zero agg
// grid BN/32, block 128; smem hs[32*128] + Ws[128*128] = 80 KB
__global__ void __launch_bounds__(NT, 2)
k_xgemm_f(const float* __restrict__ W) {
    extern __shared__ float sm[];
    float* hs = sm;                   // 32*128
    float* Ws = sm + TR * 128;        // 128*128
    int tid = threadIdx.x;
    int row0 = blockIdx.x * TR;
    {
        const float4* s4 = (const float4*)(g_h + (size_t)row0 * HID);
        float4* d4 = (float4*)hs;
        for (int i = tid; i < TR * 32; i += NT) d4[i] = s4[i];
        const float4* W4 = (const float4*)W;
        float4* Ws4 = (float4*)Ws;
        for (int i = tid; i < HID * 32; i += NT) Ws4[i] = W4[i];
    }
    __syncthreads();
    GEMM_BODY4(hs, HID)
    #pragma unroll
    for (int r = 0; r < 4; r++) {
        __half2* dst = (__half2*)(g_x + (size_t)(row0 + rg * 4 + r) * HID + cg * 8);
        dst[0] = __floats2half2_rn(acc[r][0], acc[r][1]);
        dst[1] = __floats2half2_rn(acc[r][2], acc[r][3]);
        dst[2] = __floats2half2_rn(acc[r][4], acc[r][5]);
        dst[3] = __floats2half2_rn(acc[r][6], acc[r][7]);
    }
    float4 z = {0.f, 0.f, 0.f, 0.f};
    float4* ag4 = (float4*)(g_agg + (size_t)row0 * HID);
    for (int i = tid; i < TR * 32; i += NT) ag4[i] = z;
}

// ---------------------------------------------------------------- edge scatter (warp/edge, fp16 table + fp16 x, v4 red)
__global__ void k_edge(const int* __restrict__ ei, int blk) {
    int gid  = blockIdx.x * blockDim.x + threadIdx.x;
    int e    = gid >> 5;
    int lane = gid & 31;
    if (e >= NE) return;
    float u = __ldg(&g_u[e]);
    int i0 = (int)u;
    if (i0 > TLEN - 2) i0 = TLEN - 2;
    float f = u - (float)i0;
    int s = __ldg(&ei[e]), d = __ldg(&ei[NE + e]);
    const uint2* tb = (const uint2*)(g_tab + (size_t)blk * TLEN * HID);  // 32 uint2 per row
    uint2 ua = __ldg(tb + (size_t)i0 * 32 + lane);
    uint2 ub = __ldg(tb + (size_t)(i0 + 1) * 32 + lane);
    float2 a01 = __half22float2(*reinterpret_cast<const __half2*>(&ua.x));
    float2 a23 = __half22float2(*reinterpret_cast<const __half2*>(&ua.y));
    float2 b01 = __half22float2(*reinterpret_cast<const __half2*>(&ub.x));
    float2 b23 = __half22float2(*reinterpret_cast<const __half2*>(&ub.y));
    uint2 ux = __ldg((const uint2*)(g_x + (size_t)s * HID) + lane);
    float2 x01 = __half22float2(*reinterpret_cast<const __half2*>(&ux.x));
    float2 x23 = __half22float2(*reinterpret_cast<const __half2*>(&ux.y));
    float m0 = (a01.x + f * (b01.x - a01.x)) * x01.x;
    float m1 = (a01.y + f * (b01.y - a01.y)) * x01.y;
    float m2 = (a23.x + f * (b23.x - a23.x)) * x23.x;
    float m3 = (a23.y + f * (b23.y - a23.y)) * x23.y;
    float* ag = g_agg + (size_t)d * HID + lane * 4;
    asm volatile("red.global.add.v4.f32 [%0], {%1, %2, %3, %4};"
                 :: "l"(ag), "f"(m0), "f"(m1), "f"(m2), "f"(m3) : "memory");
}

// ---------------------------------------------------------------- fused node MLP + residual + LN
//   + (if hasNext) x = h_new @ lin_in[next], re-zero agg
// grid BN/32, block 128; smem ins[32*128] + act[32*128] + Ws[128*128] = 96 KB
__global__ void __launch_bounds__(NT, 2)
k_node_f(const float* __restrict__ W1, const float* __restrict__ B1,
         const float* __restrict__ W2, const float* __restrict__ B2,
         const float* __restrict__ G,  const float* __restrict__ Bt,
         const float* __restrict__ WlinNext, int hasNext) {
    extern __shared__ float sm[];
    float* ins = sm;                    // 32*128: agg -> y -> h_new
    float* act = sm + TR * 128;         // 32*128
    float* Ws  = sm + 2 * TR * 128;     // 128*128 (reloaded up to 3x)
    int tid = threadIdx.x;
    int row0 = blockIdx.x * TR;
    {
        const float4* s4 = (const float4*)(g_agg + (size_t)row0 * HID);
        float4* d4 = (float4*)ins;
        for (int i = tid; i < TR * 32; i += NT) d4[i] = s4[i];
        const float4* W4 = (const float4*)W1;
        float4* Ws4 = (float4*)Ws;
        for (int i = tid; i < HID * 32; i += NT) Ws4[i] = W4[i];
    }
    __syncthreads();
    {
        GEMM_BODY4(ins, HID)
        float bb[8];
        #pragma unroll
        for (int c = 0; c < 8; c++) bb[c] = __ldg(&B1[cg * 8 + c]);
        #pragma unroll
        for (int r = 0; r < 4; r++)
            #pragma unroll
            for (int c = 0; c < 8; c++)
                act[(rg * 4 + r) * 128 + cg * 8 + c] = silu_f(acc[r][c] + bb[c]);
    }
    __syncthreads();
    {
        const float4* W4 = (const float4*)W2;
        float4* Ws4 = (float4*)Ws;
        for (int i = tid; i < HID * 32; i += NT) Ws4[i] = W4[i];
    }
    __syncthreads();
    {
        GEMM_BODY4(act, HID)
        float bb[8];
        #pragma unroll
        for (int c = 0; c < 8; c++) bb[c] = __ldg(&B2[cg * 8 + c]);
        // y = h + out, staged into ins for the LN pass
        #pragma unroll
        for (int r = 0; r < 4; r++) {
            int row = row0 + rg * 4 + r;
            const float* hp = g_h + (size_t)row * HID + cg * 8;
            #pragma unroll
            for (int c = 0; c < 8; c++)
                ins[(rg * 4 + r) * 128 + cg * 8 + c] = acc[r][c] + bb[c] + __ldg(&hp[c]);
        }
    }
    __syncthreads();

    // layernorm: 4 threads per row (32 rows), 32 ch each; write h_new to gmem AND ins
    {
        int r = tid >> 2, q = tid & 3;
        const float4* yr = (const float4*)(ins + r * 128 + q * 32);
        float s = 0.0f, ssq = 0.0f;
        float4 v[8];
        #pragma unroll
        for (int i = 0; i < 8; i++) {
            v[i] = yr[i];
            s   += v[i].x + v[i].y + v[i].z + v[i].w;
            ssq += v[i].x*v[i].x + v[i].y*v[i].y + v[i].z*v[i].z + v[i].w*v[i].w;
        }
        s   += __shfl_xor_sync(0xffffffffu, s, 1);
        ssq += __shfl_xor_sync(0xffffffffu, ssq, 1);
        s   += __shfl_xor_sync(0xffffffffu, s, 2);
        ssq += __shfl_xor_sync(0xffffffffu, ssq, 2);
        float mu = s * (1.0f / HID);
        float var = ssq * (1.0f / HID) - mu * mu;
        float rstd = rsqrtf(var + 1e-5f);
        float4* outp = (float4*)(g_h + (size_t)(row0 + r) * HID + q * 32);
        float4* insp = (float4*)(ins + r * 128 + q * 32);
        const float4* G4 = (const float4*)(G + q * 32);
        const float4* B4 = (const float4*)(Bt + q * 32);
        #pragma unroll
        for (int i = 0; i < 8; i++) {
            float4 gv = __ldg(&G4[i]);
            float4 bv = __ldg(&B4[i]);
            float4 o;
            o.x = (v[i].x - mu) * rstd * gv.x + bv.x;
            o.y = (v[i].y - mu) * rstd * gv.y + bv.y;
            o.z = (v[i].z - mu) * rstd * gv.z + bv.z;
            o.w = (v[i].w - mu) * rstd * gv.w + bv.w;
            outp[i] = o;
            insp[i] = o;
        }
    }

    if (!hasNext) return;

    // epilogue: x = h_new @ lin_in[next] (fp16 out); re-zero agg tile
    __syncthreads();
    {
        const float4* W4 = (const float4*)WlinNext;
        float4* Ws4 = (float4*)Ws;
        for (int i = tid; i < HID * 32; i += NT) Ws4[i] = W4[i];
    }
    __syncthreads();
    {
        GEMM_BODY4(ins, HID)
        #pragma unroll
        for (int r = 0; r < 4; r++) {
            __half2* dst = (__half2*)(g_x + (size_t)(row0 + rg * 4 + r) * HID + cg * 8);
            dst[0] = __floats2half2_rn(acc[r][0], acc[r][1]);
            dst[1] = __floats2half2_rn(acc[r][2], acc[r][3]);
            dst[2] = __floats2half2_rn(acc[r][4], acc[r][5]);
            dst[3] = __floats2half2_rn(acc[r][6], acc[r][7]);
        }
    }
    float4 z = {0.f, 0.f, 0.f, 0.f};
    float4* ag4 = (float4*)(g_agg + (size_t)row0 * HID);
    for (int i = tid; i < TR * 32; i += NT) ag4[i] = z;
}

// ---------------------------------------------------------------- output zero + readout
__global__ void k_zero_out(float* out) {
    if (threadIdx.x < 64) out[threadIdx.x] = 0.0f;
}

__global__ void k_readout(const float* __restrict__ w1, const float* __restrict__ b1v,
                          const float* __restrict__ w2, const float* __restrict__ b2v,
                          float* __restrict__ out) {
    __shared__ float s[HID];
    __shared__ float part[2];
    int n = blockIdx.x, t = threadIdx.x;   // 64 threads
    float h0 = g_h[n * HID + t];
    float h1 = g_h[n * HID + 64 + t];
    s[t]      = silu_f(h0);
    s[64 + t] = silu_f(h1);
    __syncthreads();
    float a = b1v[t];
    #pragma unroll 8
    for (int k = 0; k < HID; k++) a += s[k] * w1[k * 64 + t];
    float v = silu_f(a) * w2[t];
    #pragma unroll
    for (int off = 16; off > 0; off >>= 1) v += __shfl_down_sync(0xffffffffu, v, off);
    if ((t & 31) == 0) part[t >> 5] = v;
    __syncthreads();
    if (t == 0) atomicAdd(&out[n >> 7], part[0] + part[1] + b2v[0]);
}

// ---------------------------------------------------------------- launch
extern "C" void kernel_launch(void* const* d_in, const int* in_sizes, int n_in,
                              void* d_out, int out_size) {
    const int*   Z       = (const int*)  d_in[0];
    const float* pos     = (const float*)d_in[1];
    const int*   ei      = (const int*)  d_in[2];
    const float* embed_w = (const float*)d_in[3];
    const float* ew1     = (const float*)d_in[4];
    const float* eb1     = (const float*)d_in[5];
    const float* ew2     = (const float*)d_in[6];
    const float* eb2     = (const float*)d_in[7];
    const float* linw    = (const float*)d_in[8];
    const float* nw1     = (const float*)d_in[9];
    const float* nb1     = (const float*)d_in[10];
    const float* nw2     = (const float*)d_in[11];
    const float* nb2     = (const float*)d_in[12];
    const float* lng     = (const float*)d_in[13];
    const float* lnb     = (const float*)d_in[14];
    const float* row1    = (const float*)d_in[15];
    const float* rob1    = (const float*)d_in[16];
    const float* row2    = (const float*)d_in[17];
    const float* rob2    = (const float*)d_in[18];
    float* out = (float*)d_out;

    const int SM_TABLE = (TR*64 + TR*128 + 128*128) * (int)sizeof(float);   // 88 KB
    const int SM_XGEMM = (TR*128 + 128*128) * (int)sizeof(float);           // 80 KB
    const int SM_NODE  = (2*TR*128 + 128*128) * (int)sizeof(float);         // 96 KB
    cudaFuncSetAttribute(k_table_f, cudaFuncAttributeMaxDynamicSharedMemorySize, SM_TABLE);
    cudaFuncSetAttribute(k_xgemm_f, cudaFuncAttributeMaxDynamicSharedMemorySize, SM_XGEMM);
    cudaFuncSetAttribute(k_node_f,  cudaFuncAttributeMaxDynamicSharedMemorySize, SM_NODE);

    k_embed<<<BN, HID>>>(Z, embed_w);
    k_dist<<<(NE + 255) / 256, 256>>>(ei, pos);
    dim3 tg(TLEN / TR, NBLK);
    k_table_f<<<tg, NT, SM_TABLE>>>(ew1, eb1, ew2, eb2);

    // block 0 prologue: x = h @ lin_in[0], zero agg
    k_xgemm_f<<<BN / TR, NT, SM_XGEMM>>>(linw);

    for (int b = 0; b < NBLK; b++) {
        k_edge<<<NE / 8, 256>>>(ei, b);
        int hasNext = (b + 1 < NBLK) ? 1 : 0;
        const float* wnext = hasNext ? (linw + (b + 1) * HID * HID) : linw;
        k_node_f<<<BN / TR, NT, SM_NODE>>>(
            nw1 + b * HID * HID, nb1 + b * HID,
            nw2 + b * HID * HID, nb2 + b * HID,
            lng + b * HID, lnb + b * HID,
            wnext, hasNext);
    }

    k_zero_out<<<1, 64>>>(out);
    k_readout<<<BN, 64>>>(row1, rob1, row2, rob2, out);
}

// round 11
// speedup vs baseline: 1.3858x; 1.0171x over previous
#include <cuda_runtime.h>
#include <cuda_fp16.h>
#include <math.h>

#define BN    8192
#define HID   128
#define NE    262144
#define NRBF  64
#define NBLK  4
#define TLEN  512
#define RCUTF 6.0f
#define GAMMAF (10.0f/36.0f)
#define NT    128          // threads per GEMM block
#define TR    32           // rows per GEMM tile

// ---- scratch (device globals: allocation-free) ----
__device__ float  g_h[BN * HID];
__device__ __half g_x[BN * HID];                // fp16 x = h @ lin_in
__device__ float  g_agg[BN * HID];
__device__ float  g_u[NE];
__device__ __half g_tab[NBLK * TLEN * HID];     // 512 KB total; 128 KB per block -> L1-resident

__device__ __forceinline__ float silu_f(float v) { return v / (1.0f + expf(-v)); }

// ---------------------------------------------------------------- distances -> table coord
__global__ void k_dist(const int* __restrict__ ei, const float* __restrict__ pos) {
    int e = blockIdx.x * blockDim.x + threadIdx.x;
    if (e >= NE) return;
    int s = ei[e], d = ei[NE + e];
    float dx = pos[3*s]   - pos[3*d];
    float dy = pos[3*s+1] - pos[3*d+1];
    float dz = pos[3*s+2] - pos[3*d+2];
    float dd = sqrtf(dx*dx + dy*dy + dz*dz);
    dd = fminf(dd, RCUTF);
    g_u[e] = dd * ((float)(TLEN - 1) / RCUTF);
}

// ================================================================
// GEMM tiles: 32 rows x 128 cols, 128 threads, thread tile 4x8 (proven ILP shape).
// cg = tid&15 (cols cg*8..+7), rg = tid>>4 in 0..7 (rows rg*4..+3)
// ================================================================

#define GEMM_BODY4(SRC, KDIM)                                             \
    int cg = tid & 15, rg = tid >> 4;                                     \
    float acc[4][8];                                                      \
    _Pragma("unroll")                                                     \
    for (int r = 0; r < 4; r++)                                           \
        _Pragma("unroll")                                                 \
        for (int c = 0; c < 8; c++) acc[r][c] = 0.0f;                     \
    _Pragma("unroll 4")                                                   \
    for (int k = 0; k < KDIM; k++) {                                      \
        float4 w0 = ((const float4*)(Ws + k * 128))[cg * 2];              \
        float4 w1v = ((const float4*)(Ws + k * 128))[cg * 2 + 1];         \
        _Pragma("unroll")                                                 \
        for (int r = 0; r < 4; r++) {                                     \
            float a = SRC[(rg * 4 + r) * KDIM + k];                       \
            acc[r][0] += a * w0.x;  acc[r][1] += a * w0.y;                \
            acc[r][2] += a * w0.z;  acc[r][3] += a * w0.w;                \
            acc[r][4] += a * w1v.x; acc[r][5] += a * w1v.y;               \
            acc[r][6] += a * w1v.z; acc[r][7] += a * w1v.w;               \
        }                                                                 \
    }

// ---------------------------------------------------------------- tables: w_i(d), fp16 out
// grid (TLEN/32, NBLK), block 128; smem rbf[32*64] + act[32*128] + Ws[128*128] = 88 KB
__global__ void __launch_bounds__(NT, 2)
k_table_f(const float* __restrict__ w1, const float* __restrict__ b1,
          const float* __restrict__ w2, const float* __restrict__ b2) {
    extern __shared__ float sm[];
    float* rbfs = sm;                    // 32*64
    float* act  = sm + 32*64;            // 32*128
    float* Ws   = sm + 32*64 + 32*128;   // 128*128
    int tid = threadIdx.x;
    int blk = blockIdx.y;
    int t0  = blockIdx.x * TR;
    const float DSTEP = RCUTF / (float)(TLEN - 1);
    const float CSTEP = RCUTF / (float)(NRBF - 1);

    for (int i = tid; i < TR * 64; i += NT) {
        int row = i >> 6, c = i & 63;
        float d = (float)(t0 + row) * DSTEP;
        float u = d - (float)c * CSTEP;
        rbfs[i] = expf(-GAMMAF * u * u);
    }
    {
        const float4* W4 = (const float4*)(w1 + blk * NRBF * HID);
        float4* Ws4 = (float4*)Ws;
        for (int i = tid; i < NRBF * 32; i += NT) Ws4[i] = W4[i];
    }
    __syncthreads();

    {
        GEMM_BODY4(rbfs, NRBF)
        float bb[8];
        #pragma unroll
        for (int c = 0; c < 8; c++) bb[c] = __ldg(&b1[blk * HID + cg * 8 + c]);
        #pragma unroll
        for (int r = 0; r < 4; r++)
            #pragma unroll
            for (int c = 0; c < 8; c++)
                act[(rg * 4 + r) * 128 + cg * 8 + c] = silu_f(acc[r][c] + bb[c]);
    }
    __syncthreads();
    {
        const float4* W4 = (const float4*)(w2 + blk * HID * HID);
        float4* Ws4 = (float4*)Ws;
        for (int i = tid; i < HID * 32; i += NT) Ws4[i] = W4[i];
    }
    __syncthreads();
    {
        GEMM_BODY4(act, HID)
        float bb[8];
        #pragma unroll
        for (int c = 0; c < 8; c++) bb[c] = __ldg(&b2[blk * HID + cg * 8 + c]);
        #pragma unroll
        for (int r = 0; r < 4; r++) {
            __half2* dst = (__half2*)(g_tab + (size_t)(blk * TLEN + t0 + rg * 4 + r) * HID + cg * 8);
            dst[0] = __floats2half2_rn(acc[r][0] + bb[0], acc[r][1] + bb[1]);
            dst[1] = __floats2half2_rn(acc[r][2] + bb[2], acc[r][3] + bb[3]);
            dst[2] = __floats2half2_rn(acc[r][4] + bb[4], acc[r][5] + bb[5]);
            dst[3] = __floats2half2_rn(acc[r][6] + bb[6], acc[r][7] + bb[7]);
        }
    }
}

// ---------------------------------------------------------------- embed + x = h @ lin_in[0]; zero agg
// grid BN/32, block 128; smem hs[32*128] + Ws[128*128] = 80 KB
__global__ void __launch_bounds__(NT, 2)
k_xgemm_f(const float* __restrict__ W, const int* __restrict__ Z,
          const float* __restrict__ embed_w) {
    extern __shared__ float sm[];
    float* hs = sm;                   // 32*128
    float* Ws = sm + TR * 128;        // 128*128
    int tid = threadIdx.x;
    int row0 = blockIdx.x * TR;
    {
        // gather embedding rows straight into the tile; also materialize g_h
        float4* d4 = (float4*)hs;
        float4* h4 = (float4*)(g_h + (size_t)row0 * HID);
        for (int i = tid; i < TR * 32; i += NT) {
            int z = __ldg(&Z[row0 + (i >> 5)]);
            float4 v = __ldg(((const float4*)(embed_w + (size_t)z * HID)) + (i & 31));
            d4[i] = v;
            h4[i] = v;
        }
        const float4* W4 = (const float4*)W;
        float4* Ws4 = (float4*)Ws;
        for (int i = tid; i < HID * 32; i += NT) Ws4[i] = W4[i];
    }
    __syncthreads();
    GEMM_BODY4(hs, HID)
    #pragma unroll
    for (int r = 0; r < 4; r++) {
        __half2* dst = (__half2*)(g_x + (size_t)(row0 + rg * 4 + r) * HID + cg * 8);
        dst[0] = __floats2half2_rn(acc[r][0], acc[r][1]);
        dst[1] = __floats2half2_rn(acc[r][2], acc[r][3]);
        dst[2] = __floats2half2_rn(acc[r][4], acc[r][5]);
        dst[3] = __floats2half2_rn(acc[r][6], acc[r][7]);
    }
    float4 z4 = {0.f, 0.f, 0.f, 0.f};
    float4* ag4 = (float4*)(g_agg + (size_t)row0 * HID);
    for (int i = tid; i < TR * 32; i += NT) ag4[i] = z4;
}

// ---------------------------------------------------------------- edge scatter (warp/edge, L1-resident fp16 table)
// table via __ldg (L1-cached, 128 KB footprint), x via __ldcg (L2-only), u/ei via __ldcs (streaming)
__global__ void k_edge(const int* __restrict__ ei, int blk) {
    int gid  = blockIdx.x * blockDim.x + threadIdx.x;
    int e    = gid >> 5;
    int lane = gid & 31;
    if (e >= NE) return;
    float u = __ldcs(&g_u[e]);
    int i0 = (int)u;
    if (i0 > TLEN - 2) i0 = TLEN - 2;
    float f = u - (float)i0;
    int s = __ldcs(&ei[e]), d = __ldcs(&ei[NE + e]);
    const uint2* tb = (const uint2*)(g_tab + (size_t)blk * TLEN * HID);  // 32 uint2 per row
    uint2 ua = __ldg(tb + (size_t)i0 * 32 + lane);
    uint2 ub = __ldg(tb + (size_t)(i0 + 1) * 32 + lane);
    float2 a01 = __half22float2(*reinterpret_cast<const __half2*>(&ua.x));
    float2 a23 = __half22float2(*reinterpret_cast<const __half2*>(&ua.y));
    float2 b01 = __half22float2(*reinterpret_cast<const __half2*>(&ub.x));
    float2 b23 = __half22float2(*reinterpret_cast<const __half2*>(&ub.y));
    uint2 ux = __ldcg((const uint2*)(g_x + (size_t)s * HID) + lane);
    float2 x01 = __half22float2(*reinterpret_cast<const __half2*>(&ux.x));
    float2 x23 = __half22float2(*reinterpret_cast<const __half2*>(&ux.y));
    float m0 = (a01.x + f * (b01.x - a01.x)) * x01.x;
    float m1 = (a01.y + f * (b01.y - a01.y)) * x01.y;
    float m2 = (a23.x + f * (b23.x - a23.x)) * x23.x;
    float m3 = (a23.y + f * (b23.y - a23.y)) * x23.y;
    float* ag = g_agg + (size_t)d * HID + lane * 4;
    asm volatile("red.global.add.v4.f32 [%0], {%1, %2, %3, %4};"
                 :: "l"(ag), "f"(m0), "f"(m1), "f"(m2), "f"(m3) : "memory");
}

// ---------------------------------------------------------------- fused node MLP + residual + LN
//   + (if hasNext) x = h_new @ lin_in[next], re-zero agg
// grid BN/32, block 128; smem ins[32*128] + act[32*128] + Ws[128*128] = 96 KB
__global__ void __launch_bounds__(NT, 2)
k_node_f(const float* __restrict__ W1, const float* __restrict__ B1,
         const float* __restrict__ W2, const float* __restrict__ B2,
         const float* __restrict__ G,  const float* __restrict__ Bt,
         const float* __restrict__ WlinNext, int hasNext) {
    extern __shared__ float sm[];
    float* ins = sm;                    // 32*128: agg -> y -> h_new
    float* act = sm + TR * 128;         // 32*128
    float* Ws  = sm + 2 * TR * 128;     // 128*128 (reloaded up to 3x)
    int tid = threadIdx.x;
    int row0 = blockIdx.x * TR;
    {
        const float4* s4 = (const float4*)(g_agg + (size_t)row0 * HID);
        float4* d4 = (float4*)ins;
        for (int i = tid; i < TR * 32; i += NT) d4[i] = s4[i];
        const float4* W4 = (const float4*)W1;
        float4* Ws4 = (float4*)Ws;
        for (int i = tid; i < HID * 32; i += NT) Ws4[i] = W4[i];
    }
    __syncthreads();
    {
        GEMM_BODY4(ins, HID)
        float bb[8];
        #pragma unroll
        for (int c = 0; c < 8; c++) bb[c] = __ldg(&B1[cg * 8 + c]);
        #pragma unroll
        for (int r = 0; r < 4; r++)
            #pragma unroll
            for (int c = 0; c < 8; c++)
                act[(rg * 4 + r) * 128 + cg * 8 + c] = silu_f(acc[r][c] + bb[c]);
    }
    __syncthreads();
    {
        const float4* W4 = (const float4*)W2;
        float4* Ws4 = (float4*)Ws;
        for (int i = tid; i < HID * 32; i += NT) Ws4[i] = W4[i];
    }
    __syncthreads();
    {
        GEMM_BODY4(act, HID)
        float bb[8];
        #pragma unroll
        for (int c = 0; c < 8; c++) bb[c] = __ldg(&B2[cg * 8 + c]);
        // y = h + out, staged into ins for the LN pass
        #pragma unroll
        for (int r = 0; r < 4; r++) {
            int row = row0 + rg * 4 + r;
            const float* hp = g_h + (size_t)row * HID + cg * 8;
            #pragma unroll
            for (int c = 0; c < 8; c++)
                ins[(rg * 4 + r) * 128 + cg * 8 + c] = acc[r][c] + bb[c] + __ldg(&hp[c]);
        }
    }
    __syncthreads();

    // layernorm: 4 threads per row (32 rows), 32 ch each; write h_new to gmem AND ins
    {
        int r = tid >> 2, q = tid & 3;
        const float4* yr = (const float4*)(ins + r * 128 + q * 32);
        float s = 0.0f, ssq = 0.0f;
        float4 v[8];
        #pragma unroll
        for (int i = 0; i < 8; i++) {
            v[i] = yr[i];
            s   += v[i].x + v[i].y + v[i].z + v[i].w;
            ssq += v[i].x*v[i].x + v[i].y*v[i].y + v[i].z*v[i].z + v[i].w*v[i].w;
        }
        s   += __shfl_xor_sync(0xffffffffu, s, 1);
        ssq += __shfl_xor_sync(0xffffffffu, ssq, 1);
        s   += __shfl_xor_sync(0xffffffffu, s, 2);
        ssq += __shfl_xor_sync(0xffffffffu, ssq, 2);
        float mu = s * (1.0f / HID);
        float var = ssq * (1.0f / HID) - mu * mu;
        float rstd = rsqrtf(var + 1e-5f);
        float4* outp = (float4*)(g_h + (size_t)(row0 + r) * HID + q * 32);
        float4* insp = (float4*)(ins + r * 128 + q * 32);
        const float4* G4 = (const float4*)(G + q * 32);
        const float4* B4 = (const float4*)(Bt + q * 32);
        #pragma unroll
        for (int i = 0; i < 8; i++) {
            float4 gv = __ldg(&G4[i]);
            float4 bv = __ldg(&B4[i]);
            float4 o;
            o.x = (v[i].x - mu) * rstd * gv.x + bv.x;
            o.y = (v[i].y - mu) * rstd * gv.y + bv.y;
            o.z = (v[i].z - mu) * rstd * gv.z + bv.z;
            o.w = (v[i].w - mu) * rstd * gv.w + bv.w;
            outp[i] = o;
            insp[i] = o;
        }
    }

    if (!hasNext) return;

    // epilogue: x = h_new @ lin_in[next] (fp16 out); re-zero agg tile
    __syncthreads();
    {
        const float4* W4 = (const float4*)WlinNext;
        float4* Ws4 = (float4*)Ws;
        for (int i = tid; i < HID * 32; i += NT) Ws4[i] = W4[i];
    }
    __syncthreads();
    {
        GEMM_BODY4(ins, HID)
        #pragma unroll
        for (int r = 0; r < 4; r++) {
            __half2* dst = (__half2*)(g_x + (size_t)(row0 + rg * 4 + r) * HID + cg * 8);
            dst[0] = __floats2half2_rn(acc[r][0], acc[r][1]);
            dst[1] = __floats2half2_rn(acc[r][2], acc[r][3]);
            dst[2] = __floats2half2_rn(acc[r][4], acc[r][5]);
            dst[3] = __floats2half2_rn(acc[r][6], acc[r][7]);
        }
    }
    float4 z4 = {0.f, 0.f, 0.f, 0.f};
    float4* ag4 = (float4*)(g_agg + (size_t)row0 * HID);
    for (int i = tid; i < TR * 32; i += NT) ag4[i] = z4;
}

// ---------------------------------------------------------------- output zero + readout
__global__ void k_zero_out(float* out) {
    if (threadIdx.x < 64) out[threadIdx.x] = 0.0f;
}

__global__ void k_readout(const float* __restrict__ w1, const float* __restrict__ b1v,
                          const float* __restrict__ w2, const float* __restrict__ b2v,
                          float* __restrict__ out) {
    __shared__ float s[HID];
    __shared__ float part[2];
    int n = blockIdx.x, t = threadIdx.x;   // 64 threads
    float h0 = g_h[n * HID + t];
    float h1 = g_h[n * HID + 64 + t];
    s[t]      = silu_f(h0);
    s[64 + t] = silu_f(h1);
    __syncthreads();
    float a = b1v[t];
    #pragma unroll 8
    for (int k = 0; k < HID; k++) a += s[k] * w1[k * 64 + t];
    float v = silu_f(a) * w2[t];
    #pragma unroll
    for (int off = 16; off > 0; off >>= 1) v += __shfl_down_sync(0xffffffffu, v, off);
    if ((t & 31) == 0) part[t >> 5] = v;
    __syncthreads();
    if (t == 0) atomicAdd(&out[n >> 7], part[0] + part[1] + b2v[0]);
}

// ---------------------------------------------------------------- launch
extern "C" void kernel_launch(void* const* d_in, const int* in_sizes, int n_in,
                              void* d_out, int out_size) {
    const int*   Z       = (const int*)  d_in[0];
    const float* pos     = (const float*)d_in[1];
    const int*   ei      = (const int*)  d_in[2];
    const float* embed_w = (const float*)d_in[3];
    const float* ew1     = (const float*)d_in[4];
    const float* eb1     = (const float*)d_in[5];
    const float* ew2     = (const float*)d_in[6];
    const float* eb2     = (const float*)d_in[7];
    const float* linw    = (const float*)d_in[8];
    const float* nw1     = (const float*)d_in[9];
    const float* nb1     = (const float*)d_in[10];
    const float* nw2     = (const float*)d_in[11];
    const float* nb2     = (const float*)d_in[12];
    const float* lng     = (const float*)d_in[13];
    const float* lnb     = (const float*)d_in[14];
    const float* row1    = (const float*)d_in[15];
    const float* rob1    = (const float*)d_in[16];
    const float* row2    = (const float*)d_in[17];
    const float* rob2    = (const float*)d_in[18];
    float* out = (float*)d_out;

    const int SM_TABLE = (TR*64 + TR*128 + 128*128) * (int)sizeof(float);   // 88 KB
    const int SM_XGEMM = (TR*128 + 128*128) * (int)sizeof(float);           // 80 KB
    const int SM_NODE  = (2*TR*128 + 128*128) * (int)sizeof(float);         // 96 KB
    cudaFuncSetAttribute(k_table_f, cudaFuncAttributeMaxDynamicSharedMemorySize, SM_TABLE);
    cudaFuncSetAttribute(k_xgemm_f, cudaFuncAttributeMaxDynamicSharedMemorySize, SM_XGEMM);
    cudaFuncSetAttribute(k_node_f,  cudaFuncAttributeMaxDynamicSharedMemorySize, SM_NODE);

    k_dist<<<(NE + 255) / 256, 256>>>(ei, pos);
    dim3 tg(TLEN / TR, NBLK);
    k_table_f<<<tg, NT, SM_TABLE>>>(ew1, eb1, ew2, eb2);

    // prologue: embed -> h, x = h @ lin_in[0], zero agg
    k_xgemm_f<<<BN / TR, NT, SM_XGEMM>>>(linw, Z, embed_w);

    for (int b = 0; b < NBLK; b++) {
        k_edge<<<NE / 8, 256>>>(ei, b);
        int hasNext = (b + 1 < NBLK) ? 1 : 0;
        const float* wnext = hasNext ? (linw + (b + 1) * HID * HID) : linw;
        k_node_f<<<BN / TR, NT, SM_NODE>>>(
            nw1 + b * HID * HID, nb1 + b * HID,
            nw2 + b * HID * HID, nb2 + b * HID,
            lng + b * HID, lnb + b * HID,
            wnext, hasNext);
    }

    k_zero_out<<<1, 64>>>(out);
    k_readout<<<BN, 64>>>(row1, rob1, row2, rob2, out);
}